// round 7
// baseline (speedup 1.0000x reference)
#include <cuda_runtime.h>

// Problem constants (fixed by the reference).
#define B_DIM   16384
#define T_DIM   512
#define HOR     32
#define NSTEP   (T_DIM + B_DIM - 1)   // 16895 scan steps
#define NPAD    16896                 // 132 * 128, padded for unguarded float4 I/O
#define NBLK    132                   // blocks of 128 steps (= queue depth M)

// Scratch (allocation-free rule: __device__ globals; zero-initialized).
__device__ float g_ts[NPAD];
__device__ float g_xnorm[NPAD];
__device__ float g_levels[NPAD];
__device__ float g_sseq[NPAD];
__device__ int   g_flag[NBLK];        // chunk-ready flags (self-cleaned each run)
__device__ int   g_done;              // producer completion counter

__device__ __forceinline__ float frcp(float x) {
    float r;
    asm("rcp.approx.ftz.f32 %0, %1;" : "=f"(r) : "f"(x));
    return r;
}

__device__ __forceinline__ void spin_flag(const int* p) {
    const volatile int* vp = (const volatile int*)p;
    while (*vp == 0) { }
    __threadfence();                  // acquire: order g_ts reads after flag
}
__device__ __forceinline__ void spin_done() {
    const volatile int* vp = (const volatile int*)&g_done;
    while (*vp < NBLK) { }
    __threadfence();
}

// ---------------------------------------------------------------------------
// Fused gather + scan. Grid = 133 blocks x 128 threads, all resident
// (133 <= 148 SMs) -> producers never depend on the spinning scanner.
//
// Blocks 1..132: gather chunk j=(blockIdx-1) of the effective series
//   ts[i] = x[0,i,0] (i<512) else x[i-511,511,0]; pad -> 1
// then release-publish flag[j] and bump g_done.
//
// Block 0 / warp 0: single-warp blocked scan, 132 blocks of 128 steps
// (= seasonality queue depth). l_t = c_t + k*l_{t-1}, c_t = a*y_t/s_t,
// k = 1-alpha -> Kogge-Stone over 32 lane aggregates, stage coeffs k^(4*2^d).
//   * carry folded into lane0's scan input -> I is the TRUE level at the
//     lane's last step; next carry = I_31; no post-scan carry FMA
//   * l2,l1,l0 ALL backward: l_{j-1} = fmaf(rk, l_j, -c_j*rk) (+4 cyc each;
//     the lp-shuffle is gone from the kernel entirely)
//   * stages with coefficient < 1e-5 skipped (uniform branch; contribution
//     bounded by ~2e-5 relative, threshold is 1e-3)
//   * d/rcp ordered rd1, rd0 first (they gate the next aggregate tree)
//   * scanner spins on flag[blk+3] for blk<13, then once on g_done; after
//     that g_ts prefetches (L2-hot) are unguarded
// Scanner resets flags at the end (it finishes last) -> graph replays clean.
// ---------------------------------------------------------------------------
__global__ void __launch_bounds__(128, 1)
fused_kernel(const float* __restrict__ x,
             const float* __restrict__ alpha, const float* __restrict__ gamma,
             const float* __restrict__ init_s, const float* __restrict__ level0) {
    if (blockIdx.x != 0) {
        // ---- producer: gather one 128-element chunk ----
        const int j = blockIdx.x - 1;
        const int i = j * 128 + threadIdx.x;
        float v;
        if (i < T_DIM)       v = __ldg(x + i);
        else if (i < NSTEP)  v = __ldg(x + (i - (T_DIM - 1)) * T_DIM + (T_DIM - 1));
        else                 v = 1.0f;
        g_ts[i] = v;
        __threadfence();                       // my store visible gpu-wide
        __syncthreads();                       // whole chunk written
        if (threadIdx.x == 0) {
            g_flag[j] = 1;                     // publish (fences above = release)
            __threadfence();
            atomicAdd(&g_done, 1);
        }
        return;
    }
    if (threadIdx.x >= 32) return;             // scanner = warp 0 only

    const unsigned FULL = 0xFFFFFFFFu;
    const int lane = threadIdx.x;
    const int t0 = lane * 4;

    const float a   = alpha[0];
    const float g   = gamma[0];
    const float k   = 1.0f - a;
    const float omg = 1.0f - g;
    const float k2 = k * k, k4 = k2 * k2;
    const float rk = 1.0f / k;                 // one-time precise divide
    const float K0 = k4, K1 = K0 * K0, K2c = K1 * K1, K3 = K2c * K2c, K4 = K3 * K3;
    const float EPS = 1e-5f;
    const bool on2 = (K1 > EPS), on3 = (K2c > EPS), on4 = (K3 > EPS), on5 = (K4 > EPS);

    float Tc = level0[0];                      // carry = level entering block

    // Wait for chunks 0..2, then prime the 3-deep y pipeline.
    spin_flag(&g_flag[0]); spin_flag(&g_flag[1]); spin_flag(&g_flag[2]);
    float4 ynv = *reinterpret_cast<const float4*>(g_ts + 128 + t0);
    float4 ynn = *reinterpret_cast<const float4*>(g_ts + 256 + t0);
    float4 yv  = *reinterpret_cast<const float4*>(g_ts + t0);
    float y0 = yv.x,  y1 = yv.y,  y2 = yv.z,  y3 = yv.w;
    float yn0 = ynv.x, yn1 = ynv.y, yn2 = ynv.z, yn3 = ynv.w;

    // Initial seasonality queue (block 0 of the scan uses init_s directly).
    float4 sv = *reinterpret_cast<const float4*>(init_s + t0);
    float rs0 = frcp(sv.x), rs1 = frcp(sv.y), rs2 = frcp(sv.z), rs3 = frcp(sv.w);
    float c0 = (a * y0) * rs0, c1 = (a * y1) * rs1;
    float c2 = (a * y2) * rs2, c3 = (a * y3) * rs3;
    float ncrk1 = -(c1 * rk), ncrk2 = -(c2 * rk), ncrk3 = -(c3 * rk);
    float gy0 = g * y0, gy1 = g * y1, gy2 = g * y2, gy3 = g * y3;
    float os0 = omg * sv.x, os1 = omg * sv.y, os2 = omg * sv.z, os3 = omg * sv.w;
    float ayn0 = a * yn0, ayn1 = a * yn1, ayn2 = a * yn2, ayn3 = a * yn3;

    #pragma unroll 2
    for (int blk = 0; blk < NBLK; ++blk) {
        const int base = blk * 128 + t0;

        // Readiness: per-chunk for the first prefetches, then one counter spin.
        if (blk < 13)       spin_flag(&g_flag[blk + 3]);
        else if (blk == 13) spin_done();

        // Prefetch y for block blk+3 (consumed two iterations from now).
        float4 yf = make_float4(1.f, 1.f, 1.f, 1.f);
        if (blk + 3 < NBLK)
            yf = *reinterpret_cast<const float4*>(g_ts + base + 384);

        // Aggregate tree + carry fold (all operands early).
        const float t1raw = fmaf(k, c2, c3);
        const float t2e   = fmaf(k, c0, c1);
        const float t1    = (lane == 0) ? fmaf(k4, Tc, t1raw) : t1raw;
        float I = fmaf(k2, t2e, t1);           // scan input (= P3 [+ k4*L])

        // Warp inclusive scan; stages with negligible coefficient skipped.
        float t;
        t = __shfl_up_sync(FULL, I, 1);  if (lane >= 1)  I = fmaf(K0,  t, I);
        if (on2) { t = __shfl_up_sync(FULL, I, 2);  if (lane >= 2)  I = fmaf(K1,  t, I); }
        if (on3) { t = __shfl_up_sync(FULL, I, 4);  if (lane >= 4)  I = fmaf(K2c, t, I); }
        if (on4) { t = __shfl_up_sync(FULL, I, 8);  if (lane >= 8)  I = fmaf(K3,  t, I); }
        if (on5) { t = __shfl_up_sync(FULL, I, 16); if (lane >= 16) I = fmaf(K4,  t, I); }

        // Levels, fully backward: l_{j-1} = rk*l_j - rk*c_j (one FMA each).
        const float l3 = I;
        const float l2 = fmaf(rk, l3, ncrk3);
        const float l1 = fmaf(rk, l2, ncrk2);
        const float l0 = fmaf(rk, l1, ncrk1);

        // d = g*y + (1-g)*s*l ; rd1/rd0 first (they gate the next tree).
        const float d1 = fmaf(os1, l1, gy1);
        const float rd1 = frcp(d1);
        const float d0 = fmaf(os0, l0, gy0);
        const float rd0 = frcp(d0);
        const float d2 = fmaf(os2, l2, gy2);
        const float d3 = fmaf(os3, l3, gy3);
        const float rd2 = frcp(d2), rd3 = frcp(d3);

        // m = a*y'*l overlaps MUFU latency; nc = next block's c.
        const float m0 = ayn0 * l0, m1 = ayn1 * l1;
        const float m2 = ayn2 * l2, m3 = ayn3 * l3;
        const float nc0 = m0 * rd0, nc1 = m1 * rd1;
        const float nc2 = m2 * rd2, nc3 = m3 * rd3;

        Tc = __shfl_sync(FULL, I, 31);         // next carry (off-path)

        // Off-path: outputs.
        const float rl0 = frcp(l0), rl1 = frcp(l1), rl2 = frcp(l2), rl3 = frcp(l3);
        const float sn0 = d0 * rl0, sn1 = d1 * rl1, sn2 = d2 * rl2, sn3 = d3 * rl3;
        const float xn0 = (y0 * rs0) * rl0;
        const float xn1 = (y1 * rs1) * rl1;
        const float xn2 = (y2 * rs2) * rl2;
        const float xn3 = (y3 * rs3) * rl3;

        *reinterpret_cast<float4*>(g_xnorm  + base) = make_float4(xn0, xn1, xn2, xn3);
        *reinterpret_cast<float4*>(g_levels + base) = make_float4(l0, l1, l2, l3);
        *reinterpret_cast<float4*>(g_sseq   + base) = make_float4(sn0, sn1, sn2, sn3);

        // Rotate state (distance-128 queue lives in registers).
        rs0 = l0 * rd0; rs1 = l1 * rd1; rs2 = l2 * rd2; rs3 = l3 * rd3;  // 1/s_new
        os0 = omg * sn0; os1 = omg * sn1; os2 = omg * sn2; os3 = omg * sn3;
        c0 = nc0; c1 = nc1; c2 = nc2; c3 = nc3;
        ncrk1 = -(nc1 * rk); ncrk2 = -(nc2 * rk); ncrk3 = -(nc3 * rk);
        gy0 = g * yn0; gy1 = g * yn1; gy2 = g * yn2; gy3 = g * yn3;
        y0 = yn0; y1 = yn1; y2 = yn2; y3 = yn3;
        yn0 = ynn.x; yn1 = ynn.y; yn2 = ynn.z; yn3 = ynn.w;
        ayn0 = a * yn0; ayn1 = a * yn1; ayn2 = a * yn2; ayn3 = a * yn3;
        ynn = yf;
    }

    // Self-clean for the next graph replay (producers are provably done:
    // we spun past g_done == NBLK).
    for (int j = lane; j < NBLK; j += 32) g_flag[j] = 0;
    if (lane == 0) g_done = 0;
}

// ---------------------------------------------------------------------------
// Materialize outputs. One thread serves FOUR batch rows at one t-quad:
// rows 4*b4..4*b4+3 at t=4q all read the 7-float window xnorm[4*(b4+q)..+6]
// = two ALIGNED float4. Denorm part in grid tail.
// ---------------------------------------------------------------------------
#define XTASKS ((B_DIM / 4) * (T_DIM / 4))     // 524288
#define DTASKS (B_DIM * (HOR / 2))             // 262144

__global__ void __launch_bounds__(256)
out_kernel(float* __restrict__ out) {
    const float4* __restrict__ X4 = reinterpret_cast<const float4*>(g_xnorm);
    int gid = blockIdx.x * blockDim.x + threadIdx.x;
    if (gid < XTASKS) {
        const int b4 = gid >> 7;          // row group (4 rows)
        const int q  = gid & 127;         // t-quad
        const int i4 = b4 + q;
        const float4 A = X4[i4];
        const float4 B = X4[i4 + 1];
        const int rbase = (b4 * 4) * T_DIM + q * 4;
        *reinterpret_cast<float4*>(out + rbase)             = A;
        *reinterpret_cast<float4*>(out + rbase + T_DIM)     = make_float4(A.y, A.z, A.w, B.x);
        *reinterpret_cast<float4*>(out + rbase + 2 * T_DIM) = make_float4(A.z, A.w, B.x, B.y);
        *reinterpret_cast<float4*>(out + rbase + 3 * T_DIM) = make_float4(A.w, B.x, B.y, B.z);
    } else {
        const int j = gid - XTASKS;       // 0 .. DTASKS-1
        if (j < DTASKS) {
            const int b = j >> 4;
            const int i = j & 15;         // horizons 2i, 2i+1
            const float lvl = g_levels[b + (T_DIM - 1)];
            const float sa  = g_sseq[b + 384 + 2 * i];
            const float sb  = g_sseq[b + 385 + 2 * i];
            *reinterpret_cast<float4*>(out + B_DIM * T_DIM + b * (2 * HOR) + 4 * i) =
                make_float4(lvl, sa, lvl, sb);
        }
    }
}

// ---------------------------------------------------------------------------
// Launch. Inputs (metadata order): x, alpha, gamma, init_seasonality, level.
// ---------------------------------------------------------------------------
extern "C" void kernel_launch(void* const* d_in, const int* in_sizes, int n_in,
                              void* d_out, int out_size) {
    const float* x      = (const float*)d_in[0];
    const float* alpha  = (const float*)d_in[1];
    const float* gamma  = (const float*)d_in[2];
    const float* init_s = (const float*)d_in[3];
    const float* level  = (const float*)d_in[4];
    float* out = (float*)d_out;

    fused_kernel<<<NBLK + 1, 128>>>(x, alpha, gamma, init_s, level);
    out_kernel<<<(XTASKS + DTASKS) / 256, 256>>>(out);
}